// round 14
// baseline (speedup 1.0000x reference)
#include <cuda_runtime.h>
#include <cuda_bf16.h>
#include <math.h>
#include <stdint.h>

#define CDIM 128
#define KDIM 128
#define MT 32
#define GRID 296

__device__ double g_part[GRID];
__device__ unsigned int g_done;          // monotone ticket (never reset; % GRID)

__device__ __forceinline__ uint32_t smem_u32(const void* p) {
    uint32_t a;
    asm("{ .reg .u64 t; cvta.to.shared.u64 t, %1; cvt.u32.u64 %0, t; }" : "=r"(a) : "l"(p));
    return a;
}
__device__ __forceinline__ void ldsm4(uint32_t& r0, uint32_t& r1, uint32_t& r2,
                                      uint32_t& r3, uint32_t addr) {
    asm volatile("ldmatrix.sync.aligned.m8n8.x4.shared.b16 {%0,%1,%2,%3}, [%4];"
                 : "=r"(r0), "=r"(r1), "=r"(r2), "=r"(r3) : "r"(addr));
}
__device__ __forceinline__ void mma16816(float* c4, uint32_t a0, uint32_t a1,
                                         uint32_t a2, uint32_t a3,
                                         uint32_t b0, uint32_t b1) {
    asm volatile("mma.sync.aligned.m16n8k16.row.col.f32.bf16.bf16.f32 "
                 "{%0,%1,%2,%3}, {%4,%5,%6,%7}, {%8,%9}, {%0,%1,%2,%3};"
                 : "+f"(c4[0]), "+f"(c4[1]), "+f"(c4[2]), "+f"(c4[3])
                 : "r"(a0), "r"(a1), "r"(a2), "r"(a3), "r"(b0), "r"(b1));
}
__device__ __forceinline__ uint32_t pkbf(float a, float b) {
    __nv_bfloat162 h = __floats2bfloat162_rn(a, b);
    return *(uint32_t*)&h;
}

__global__ void __launch_bounds__(256, 2)
k_main(const float* __restrict__ x, const int* __restrict__ labels,
       const float* __restrict__ protos, const int* __restrict__ kp,
       int N, float* __restrict__ out)
{
    // static smem (~19.5 KB) -> 2 CTAs/SM by regs, no attribute call
    __shared__ __align__(128) unsigned char Xs[16384];  // [2par][2ch][32row][128B swz]
    __shared__ float  qs[128];
    __shared__ float  rowsum[3 * 32];                    // ring-3
    __shared__ float  redv[2 * 128];                     // [par][4 ng][32 row]
    __shared__ int    redi[2 * 128];
    __shared__ double wpart[8];
    __shared__ int    flag[1];

    int nt = (N + MT - 1) / MT;
    int t = threadIdx.x, wid = t >> 5, lane = t & 31;
    int g = lane >> 2, q = lane & 3;
    int mg = wid & 1, ng = wid >> 1;          // warp tile: rows mg*16+[0,16), cols ng*32+[0,32)
    int k = kp ? *kp : 128;

    uint32_t Xbase0 = smem_u32(Xs);

    // ldsm lane geometry
    int rA = (lane & 7) + ((lane >> 3) & 1) * 8;
    int cA = lane >> 4;
    int jB = ((lane >> 4) << 3) + (lane & 7);
    int cB = (lane >> 3) & 1;

    // ---- prime B fragments into registers (once): stage P chunk -> ldsm -> regs
    uint32_t Bf[64];
    #pragma unroll
    for (int ch = 0; ch < 2; ch++) {
        #pragma unroll
        for (int i = 0; i < 8; i++) {        // 2048 x 8B: 128 j x 64 c bf16, swizzled
            int idx = t + i * 256;
            int j = idx >> 4, u8 = idx & 15;
            float4 v = *(const float4*)(protos + j * CDIM + ch * 64 + u8 * 4);
            uint2 pk; pk.x = pkbf(v.x, v.y); pk.y = pkbf(v.z, v.w);
            uint32_t off = (uint32_t)(j * 128 + (((u8 >> 1) ^ (j & 7)) << 4) + (u8 & 1) * 8);
            *(uint2*)(Xs + off) = pk;
        }
        __syncthreads();
        #pragma unroll
        for (int kk = 0; kk < 4; kk++)
            #pragma unroll
            for (int i = 0; i < 2; i++) {
                int j = ng * 32 + i * 16 + jB;
                uint32_t bd = Xbase0 + (uint32_t)(j * 128 + (((kk * 2 + cB) ^ (jB & 7)) << 4));
                int o = (ch * 4 + kk) * 8 + i * 4;
                ldsm4(Bf[o], Bf[o + 1], Bf[o + 2], Bf[o + 3], bd);
            }
        __syncthreads();
    }
    if (t < 128) {                            // 0.5*||p||^2 (protos L2-hot)
        const float4* pr4 = (const float4*)(protos + t * CDIM);
        float s = 0.f;
        #pragma unroll 8
        for (int c = 0; c < 32; c++) {
            float4 v = pr4[c];
            s = fmaf(v.x, v.x, fmaf(v.y, v.y, fmaf(v.z, v.z, fmaf(v.w, v.w, s))));
        }
        qs[t] = 0.5f * s;
    }

    float pr[4];
    #pragma unroll
    for (int i = 0; i < 4; i++) pr[i] = 0.f;

    // stage tile `ti` chunk `ch` into parity buf; accumulates pr[ch*2+i]
    auto stage = [&](int ti, int ch, int buf) {
        unsigned char* xb = Xs + buf * 8192 + ch * 4096;
        #pragma unroll
        for (int i = 0; i < 2; i++) {
            int idx = t + i * 256;            // 0..511 float4s (32 rows x 16)
            int row = idx >> 4, seg = idx & 15;
            int grow = ti * MT + row; if (grow >= N) grow = N - 1;
            float4 v = *(const float4*)(x + (size_t)grow * CDIM + ch * 64 + seg * 4);
            pr[ch * 2 + i] += (__expf(v.x) + __expf(v.y)) + (__expf(v.z) + __expf(v.w));
            uint2 pk; pk.x = pkbf(v.x, v.y); pk.y = pkbf(v.z, v.w);
            uint32_t off = (uint32_t)(row * 128 + (((seg >> 1) ^ (row & 7)) << 4) + (seg & 1) * 8);
            *(uint2*)(xb + off) = pk;
        }
    };

    // ---- prologue: stage T0 into buf0, rowsum ring 0, labels(T0)
    int labCur = 0, labPrev = 0;
    {
        int ti0 = blockIdx.x;
        if (t < MT && ti0 < nt) labCur = labels[ti0 * MT + t];
        if (ti0 < nt) { stage(ti0, 0, 0); stage(ti0, 1, 0); }
        #pragma unroll
        for (int i = 0; i < 2; i++) {
            float s = pr[i] + pr[2 + i];
            #pragma unroll
            for (int o = 8; o; o >>= 1) s += __shfl_xor_sync(0xffffffffu, s, o, 16);
            if ((t & 15) == 0) rowsum[(t >> 4) + i * 16] = s;
        }
        #pragma unroll
        for (int i = 0; i < 4; i++) pr[i] = 0.f;
    }

    double nll_acc = 0.0;
    int it = 0;

    for (int ti = blockIdx.x; ti < nt; ti += GRID, it++) {
        int par = it & 1;
        __syncthreads();                      // X[par], rowsum(T_it), redv(T_{it-1}) ready

        // ---- CE for previous tile
        if (it > 0 && t < MT) {
            int prow = (ti - GRID) * MT + t;
            float bv = redv[(par ^ 1) * 128 + t];
            int   bj = redi[(par ^ 1) * 128 + t];
            #pragma unroll
            for (int n2 = 1; n2 < 4; n2++) {  // ng ascending = j ascending; strict >
                float v = redv[(par ^ 1) * 128 + n2 * 32 + t];
                if (v > bv) { bv = v; bj = redi[(par ^ 1) * 128 + n2 * 32 + t]; }
            }
            int leff = (labPrev <= k - 1) ? labPrev : bj;
            float xl = x[(size_t)prow * CDIM + leff];
            nll_acc += (double)(__logf(rowsum[((it - 1) % 3) * 32 + t]) - xl);
        }
        labPrev = labCur;

        float acc[4][4];
        #pragma unroll
        for (int j = 0; j < 4; j++)
            #pragma unroll
            for (int n = 0; n < 4; n++) acc[j][n] = 0.f;

        int nti = ti + GRID;
        bool ds = (nti < nt);

        #pragma unroll
        for (int ch = 0; ch < 2; ch++) {
            uint32_t Xb = Xbase0 + (uint32_t)(par * 8192 + ch * 4096);
            #pragma unroll
            for (int kk = 0; kk < 4; kk++) {
                uint32_t a0, a1, a2, a3;
                {
                    int row = mg * 16 + rA;
                    uint32_t ad = Xb + (uint32_t)(row * 128 + (((kk * 2 + cA) ^ (rA & 7)) << 4));
                    ldsm4(a0, a1, a2, a3, ad);
                }
                #pragma unroll
                for (int i = 0; i < 2; i++) {
                    int o = (ch * 4 + kk) * 8 + i * 4;
                    mma16816(acc[2 * i],     a0, a1, a2, a3, Bf[o],     Bf[o + 1]);
                    mma16816(acc[2 * i + 1], a0, a1, a2, a3, Bf[o + 2], Bf[o + 3]);
                }
            }
            if (ds) stage(nti, ch, par ^ 1);  // LDGs covered by argmax below
        }
        if (ds && t < MT) labCur = labels[nti * MT + t];

        // ---- argmax within warp's m16 x n32 block
        float bv0 = -3.0e38f, bv1 = -3.0e38f;
        int bj0 = 0, bj1 = 0;
        #pragma unroll
        for (int j = 0; j < 4; j++) {
            int c0 = ng * 32 + j * 8 + q * 2;
            float q0 = qs[c0], q1 = qs[c0 + 1];
            float s;
            s = acc[j][0] - q0; if (s > bv0) { bv0 = s; bj0 = c0; }
            s = acc[j][1] - q1; if (s > bv0) { bv0 = s; bj0 = c0 + 1; }
            s = acc[j][2] - q0; if (s > bv1) { bv1 = s; bj1 = c0; }
            s = acc[j][3] - q1; if (s > bv1) { bv1 = s; bj1 = c0 + 1; }
        }
        #pragma unroll
        for (int o = 1; o < 4; o <<= 1) {
            float v2 = __shfl_xor_sync(0xffffffffu, bv0, o, 4);
            int   j2 = __shfl_xor_sync(0xffffffffu, bj0, o, 4);
            if (v2 > bv0 || (v2 == bv0 && j2 < bj0)) { bv0 = v2; bj0 = j2; }
            v2 = __shfl_xor_sync(0xffffffffu, bv1, o, 4);
            j2 = __shfl_xor_sync(0xffffffffu, bj1, o, 4);
            if (v2 > bv1 || (v2 == bv1 && j2 < bj1)) { bv1 = v2; bj1 = j2; }
        }
        if (q == 0) {
            int row = mg * 16 + g;
            redv[par * 128 + ng * 32 + row] = bv0;     redi[par * 128 + ng * 32 + row] = bj0;
            redv[par * 128 + ng * 32 + row + 8] = bv1; redi[par * 128 + ng * 32 + row + 8] = bj1;
        }

        if (ds) {                             // rowsum(T_{it+1}) -> ring (it+1)%3
            #pragma unroll
            for (int i = 0; i < 2; i++) {
                float s = pr[i] + pr[2 + i];
                #pragma unroll
                for (int o = 8; o; o >>= 1) s += __shfl_xor_sync(0xffffffffu, s, o, 16);
                if ((t & 15) == 0) rowsum[((it + 1) % 3) * 32 + (t >> 4) + i * 16] = s;
            }
            #pragma unroll
            for (int i = 0; i < 4; i++) pr[i] = 0.f;
        }
    }

    // ---- trailing CE for the last tile
    __syncthreads();
    if (it > 0 && t < MT) {
        int itL = it - 1, parL = itL & 1;
        int prow = (blockIdx.x + itL * GRID) * MT + t;
        if (prow < N) {
            float bv = redv[parL * 128 + t];
            int   bj = redi[parL * 128 + t];
            #pragma unroll
            for (int n2 = 1; n2 < 4; n2++) {
                float v = redv[parL * 128 + n2 * 32 + t];
                if (v > bv) { bv = v; bj = redi[parL * 128 + n2 * 32 + t]; }
            }
            int leff = (labPrev <= k - 1) ? labPrev : bj;
            float xl = x[(size_t)prow * CDIM + leff];
            nll_acc += (double)(__logf(rowsum[(itL % 3) * 32 + t]) - xl);
        }
    }

    // ---- CTA partial + ticketed finalization (reset-free across replays)
    #pragma unroll
    for (int o = 16; o; o >>= 1) nll_acc += __shfl_xor_sync(0xffffffffu, nll_acc, o);
    if (lane == 0) wpart[wid] = nll_acc;
    __syncthreads();
    if (t == 0) {
        double s = 0.0;
        #pragma unroll
        for (int i = 0; i < 8; i++) s += wpart[i];
        g_part[blockIdx.x] = s;
        __threadfence();
        unsigned int tk = atomicAdd(&g_done, 1u);
        flag[0] = ((tk % (unsigned)gridDim.x) == (unsigned)gridDim.x - 1u) ? 1 : 0;
    }
    __syncthreads();
    if (flag[0]) {
        double s = 0.0;
        for (int i = t; i < GRID; i += 256) s += g_part[i];
        #pragma unroll
        for (int o = 16; o; o >>= 1) s += __shfl_xor_sync(0xffffffffu, s, o);
        if (lane == 0) wpart[wid] = s;
        __syncthreads();
        if (t == 0) {
            double f = 0.0;
            #pragma unroll
            for (int i = 0; i < 8; i++) f += wpart[i];
            out[0] = (float)(f / (double)N);
        }
    }
}

extern "C" void kernel_launch(void* const* d_in, const int* in_sizes, int n_in,
                              void* d_out, int out_size)
{
    const float* x      = (const float*)d_in[0];
    const int*   labels = (const int*)d_in[1];
    const float* protos = (const float*)d_in[2];
    const int*   kp     = (n_in > 3) ? (const int*)d_in[3] : nullptr;
    int N = in_sizes[0] / CDIM;

    k_main<<<GRID, 256>>>(x, labels, protos, kp, N, (float*)d_out);
}